// round 2
// baseline (speedup 1.0000x reference)
#include <cuda_runtime.h>
#include <cuda_bf16.h>
#include <math.h>

#define B_    2
#define S_    2048
#define DIN_  2048
#define H_    32
#define KVH_  8
#define HD_   64
#define GROUPS_ 4
#define MROWS (B_ * S_)          // 4096

// ---------------- scratch (static device arrays; no allocation) ------------
__device__ float g_q[(size_t)MROWS * H_   * HD_];   // [B,S,H,64]   32 MB
__device__ float g_k[(size_t)MROWS * KVH_ * HD_];   // [B,S,KVH,64]  8 MB
__device__ float g_v[(size_t)MROWS * KVH_ * HD_];   //               8 MB
__device__ float g_o[(size_t)MROWS * H_   * HD_];   // attn out     32 MB

// ---------------------------------------------------------------------------
// GEMM: C[M,N] = A[M,K] @ W[N,K]^T   (both A and W are K-contiguous row-major)
// BM=BN=128, BK=16, 256 threads, 8x8 microtile per thread.
// ---------------------------------------------------------------------------
__global__ void __launch_bounds__(256) gemm_nt(const float* __restrict__ A,
                                               const float* __restrict__ W,
                                               float* __restrict__ C,
                                               int M, int N, int K) {
    __shared__ float As[16][132];   // [k][m], pad 4 to soften store conflicts
    __shared__ float Ws[16][132];   // [k][n]

    const int tid = threadIdx.x;
    const int tx  = tid & 15;        // 0..15  -> N direction
    const int ty  = tid >> 4;        // 0..15  -> M direction
    const int bm  = blockIdx.y * 128;
    const int bn  = blockIdx.x * 128;

    const int c4 = tid & 3;          // which float4 of the 16-float K chunk
    const int r0 = tid >> 2;         // 0..63 (base row; +64 second half)

    float acc[8][8];
#pragma unroll
    for (int i = 0; i < 8; i++)
#pragma unroll
        for (int j = 0; j < 8; j++) acc[i][j] = 0.f;

    for (int k0 = 0; k0 < K; k0 += 16) {
#pragma unroll
        for (int half = 0; half < 2; half++) {
            const int row = r0 + half * 64;
            float4 av = *(const float4*)(A + (size_t)(bm + row) * K + k0 + c4 * 4);
            float4 wv = *(const float4*)(W + (size_t)(bn + row) * K + k0 + c4 * 4);
            As[c4 * 4 + 0][row] = av.x;  As[c4 * 4 + 1][row] = av.y;
            As[c4 * 4 + 2][row] = av.z;  As[c4 * 4 + 3][row] = av.w;
            Ws[c4 * 4 + 0][row] = wv.x;  Ws[c4 * 4 + 1][row] = wv.y;
            Ws[c4 * 4 + 2][row] = wv.z;  Ws[c4 * 4 + 3][row] = wv.w;
        }
        __syncthreads();

#pragma unroll
        for (int k = 0; k < 16; k++) {
            float a[8], w[8];
            *(float4*)&a[0] = *(const float4*)&As[k][ty * 8];
            *(float4*)&a[4] = *(const float4*)&As[k][ty * 8 + 4];
            *(float4*)&w[0] = *(const float4*)&Ws[k][tx * 8];
            *(float4*)&w[4] = *(const float4*)&Ws[k][tx * 8 + 4];
#pragma unroll
            for (int i = 0; i < 8; i++)
#pragma unroll
                for (int j = 0; j < 8; j++)
                    acc[i][j] += a[i] * w[j];
        }
        __syncthreads();
    }

#pragma unroll
    for (int i = 0; i < 8; i++) {
        float* crow = C + (size_t)(bm + ty * 8 + i) * N + bn + tx * 8;
        *(float4*)(crow)     = make_float4(acc[i][0], acc[i][1], acc[i][2], acc[i][3]);
        *(float4*)(crow + 4) = make_float4(acc[i][4], acc[i][5], acc[i][6], acc[i][7]);
    }
}

// ---------------------------------------------------------------------------
// Fused per-head RMSNorm + RoPE, in place. One warp per (b,s,head) row of 64.
// rotate_half pairs element d with d+32 (HD=64).
// ---------------------------------------------------------------------------
__global__ void __launch_bounds__(256) norm_rope(float* __restrict__ t,
                                                 const float* __restrict__ w,
                                                 const float* __restrict__ cosT,
                                                 const float* __restrict__ sinT,
                                                 int heads, int nrows) {
    const int warp = blockIdx.x * (blockDim.x >> 5) + (threadIdx.x >> 5);
    if (warp >= nrows) return;
    const int lane = threadIdx.x & 31;
    const int s = (warp / heads) % S_;

    float* row = t + (size_t)warp * HD_;
    float a = row[lane];
    float b = row[lane + 32];

    float ss = a * a + b * b;
#pragma unroll
    for (int o = 16; o > 0; o >>= 1) ss += __shfl_xor_sync(0xffffffffu, ss, o);

    const float r = rsqrtf(ss * (1.0f / 64.0f) + 1e-6f);
    const float n0 = a * r * w[lane];
    const float n1 = b * r * w[lane + 32];

    const float c0 = cosT[s * HD_ + lane];
    const float s0 = sinT[s * HD_ + lane];
    const float c1 = cosT[s * HD_ + lane + 32];
    const float s1 = sinT[s * HD_ + lane + 32];

    row[lane]      = n0 * c0 - n1 * s0;   // first half: t*cos - t2*sin
    row[lane + 32] = n1 * c1 + n0 * s1;   // second half: t*cos + t1*sin
}

// ---------------------------------------------------------------------------
// Causal flash attention, fp32. One thread per query row; BM=128 rows/CTA,
// K/V streamed in 32-key tiles through shared memory (float4 broadcast reads).
// Online softmax with one rescale per tile.
// ---------------------------------------------------------------------------
__global__ void __launch_bounds__(128) attn_kernel(const float* __restrict__ q,
                                                   const float* __restrict__ k,
                                                   const float* __restrict__ v,
                                                   float* __restrict__ o) {
    __shared__ float4 ksh[32][16];   // 32 keys x 64 floats
    __shared__ float4 vsh[32][16];

    const int t  = threadIdx.x;
    const int b  = blockIdx.z;
    const int h  = blockIdx.y;
    const int kh = h >> 2;                       // h / GROUPS (repeat_interleave)
    const int sq = blockIdx.x * 128 + t;

    const float* qrow = q + ((size_t)(b * S_ + sq) * H_ + h) * HD_;
    float qr[64];
#pragma unroll
    for (int d = 0; d < 64; d++) qr[d] = qrow[d] * 0.125f;   // HD^-0.5 = 1/8

    float acc[64];
#pragma unroll
    for (int d = 0; d < 64; d++) acc[d] = 0.f;
    float m = -1e30f, l = 0.f;

    const int hi = blockIdx.x * 128 + 128;       // causal bound for this tile
    for (int n0 = 0; n0 < hi; n0 += 32) {
        const float* kbase = k + ((size_t)(b * S_ + n0) * KVH_ + kh) * HD_;
        const float* vbase = v + ((size_t)(b * S_ + n0) * KVH_ + kh) * HD_;
#pragma unroll
        for (int i = 0; i < 4; i++) {
            const int idx = t + i * 128;
            const int row = idx >> 4, c = idx & 15;
            ksh[row][c] = *(const float4*)(kbase + (size_t)row * (KVH_ * HD_) + c * 4);
            vsh[row][c] = *(const float4*)(vbase + (size_t)row * (KVH_ * HD_) + c * 4);
        }
        __syncthreads();

        float sc[32];
        float mt = -1e30f;
#pragma unroll
        for (int j = 0; j < 32; j++) {
            float s = 0.f;
#pragma unroll
            for (int c = 0; c < 16; c++) {
                float4 kv = ksh[j][c];
                s += qr[c * 4 + 0] * kv.x + qr[c * 4 + 1] * kv.y
                   + qr[c * 4 + 2] * kv.z + qr[c * 4 + 3] * kv.w;
            }
            if (n0 + j > sq) s = -1e30f;
            sc[j] = s;
            mt = fmaxf(mt, s);
        }

        const float mnew  = fmaxf(m, mt);
        const float alpha = exp2f((m - mnew) * 1.44269504f);
        l *= alpha;
#pragma unroll
        for (int d = 0; d < 64; d++) acc[d] *= alpha;

#pragma unroll
        for (int j = 0; j < 32; j++) {
            const float p = exp2f((sc[j] - mnew) * 1.44269504f);
            l += p;
#pragma unroll
            for (int c = 0; c < 16; c++) {
                float4 vv = vsh[j][c];
                acc[c * 4 + 0] += p * vv.x;  acc[c * 4 + 1] += p * vv.y;
                acc[c * 4 + 2] += p * vv.z;  acc[c * 4 + 3] += p * vv.w;
            }
        }
        m = mnew;
        __syncthreads();
    }

    const float inv = 1.f / l;
    float* orow = o + ((size_t)(b * S_ + sq) * H_ + h) * HD_;
#pragma unroll
    for (int d = 0; d < 64; d++) orow[d] = acc[d] * inv;
}

// ---------------------------------------------------------------------------
extern "C" void kernel_launch(void* const* d_in, const int* in_sizes, int n_in,
                              void* d_out, int out_size) {
    const float* x     = (const float*)d_in[0];
    // d_in[1] = mask (unused; causal hardcoded)
    const float* cosT  = (const float*)d_in[2];
    const float* sinT  = (const float*)d_in[3];
    const float* Wq    = (const float*)d_in[4];
    const float* Wk    = (const float*)d_in[5];
    const float* Wv    = (const float*)d_in[6];
    const float* Wo    = (const float*)d_in[7];
    const float* wqn   = (const float*)d_in[8];
    const float* wkn   = (const float*)d_in[9];
    float* out = (float*)d_out;

    float *q, *k, *v, *o;
    cudaGetSymbolAddress((void**)&q, g_q);
    cudaGetSymbolAddress((void**)&k, g_k);
    cudaGetSymbolAddress((void**)&v, g_v);
    cudaGetSymbolAddress((void**)&o, g_o);

    // QKV projections
    gemm_nt<<<dim3((H_ * HD_) / 128, MROWS / 128), 256>>>(x, Wq, q, MROWS, H_ * HD_, DIN_);
    gemm_nt<<<dim3((KVH_ * HD_) / 128, MROWS / 128), 256>>>(x, Wk, k, MROWS, KVH_ * HD_, DIN_);
    gemm_nt<<<dim3((KVH_ * HD_) / 128, MROWS / 128), 256>>>(x, Wv, v, MROWS, KVH_ * HD_, DIN_);

    // fused RMSNorm + RoPE on q and k
    {
        const int qrows = MROWS * H_;
        const int krows = MROWS * KVH_;
        norm_rope<<<(qrows + 7) / 8, 256>>>(q, wqn, cosT, sinT, H_, qrows);
        norm_rope<<<(krows + 7) / 8, 256>>>(k, wkn, cosT, sinT, KVH_, krows);
    }

    // causal GQA attention
    attn_kernel<<<dim3(S_ / 128, H_, B_), 128>>>(q, k, v, o);

    // output projection
    gemm_nt<<<dim3(DIN_ / 128, MROWS / 128), 256>>>(o, Wo, out, MROWS, DIN_, H_ * HD_);
}

// round 5
// speedup vs baseline: 1.2513x; 1.2513x over previous
#include <cuda_runtime.h>
#include <cuda_bf16.h>
#include <math.h>
#include <stdint.h>

#define B_    2
#define S_    2048
#define DIN_  2048
#define H_    32
#define KVH_  8
#define HD_   64
#define GROUPS_ 4
#define MROWS (B_ * S_)          // 4096

// ---------------- scratch (static device arrays; no allocation) ------------
__device__ float g_q[(size_t)MROWS * H_   * HD_];   // [B,S,H,64]   32 MB
__device__ float g_k[(size_t)MROWS * KVH_ * HD_];   // [B,S,KVH,64]  8 MB
__device__ float g_v[(size_t)MROWS * KVH_ * HD_];   //               8 MB
__device__ float g_o[(size_t)MROWS * H_   * HD_];   // attn out     32 MB

// ---------------------------------------------------------------------------
// tf32 tensor-core GEMM: C[M,N] = A[M,K] @ W[N,K]^T  (both K-contiguous).
// BM=BN=128, BK=16, 256 threads (8 warps), warp tile 64x32 of m16n8k8 mmas.
// ---------------------------------------------------------------------------
__device__ __forceinline__ float to_tf32(float x) {
    float y;
    asm("cvt.rna.tf32.f32 %0, %1;" : "=f"(y) : "f"(x));
    return y;
}

__device__ __forceinline__ void mma_tf32(float c[4],
                                         uint32_t a0, uint32_t a1, uint32_t a2, uint32_t a3,
                                         uint32_t b0, uint32_t b1) {
    asm volatile(
        "mma.sync.aligned.m16n8k8.row.col.f32.tf32.tf32.f32 "
        "{%0,%1,%2,%3}, {%4,%5,%6,%7}, {%8,%9}, {%0,%1,%2,%3};"
        : "+f"(c[0]), "+f"(c[1]), "+f"(c[2]), "+f"(c[3])
        : "r"(a0), "r"(a1), "r"(a2), "r"(a3), "r"(b0), "r"(b1));
}

#define SST 136   // smem stride: (k*136 + m) % 32 == (k*8 + m) % 32 -> conflict-free frags

__device__ __forceinline__ void gemm_tf32_body(const float* __restrict__ A,
                                               const float* __restrict__ W,
                                               float* __restrict__ C,
                                               int M, int N, int K,
                                               int bm, int bn) {
    __shared__ float As[16][SST];   // [k][m], values pre-converted to tf32
    __shared__ float Ws[16][SST];   // [k][n]

    const int tid  = threadIdx.x;
    const int lane = tid & 31;
    const int warp = tid >> 5;
    const int gid  = lane >> 2;     // 0..7
    const int tig  = lane & 3;      // 0..3

    const int warpM = warp & 1;     // 2 warps in M
    const int warpN = warp >> 1;    // 4 warps in N
    const int rb = warpM * 64;      // warp row base within tile
    const int nb = warpN * 32;      // warp col base within tile

    float c[4][4][4];
#pragma unroll
    for (int i = 0; i < 4; i++)
#pragma unroll
        for (int j = 0; j < 4; j++)
#pragma unroll
            for (int r = 0; r < 4; r++) c[i][j][r] = 0.f;

    for (int k0 = 0; k0 < K; k0 += 16) {
        // load tiles: idx -> c4 = idx>>7 (k-chunk), row = idx&127
        // lanes cover 32 consecutive rows -> conflict-free transposed STS
#pragma unroll
        for (int it = 0; it < 2; it++) {
            const int idx = tid + it * 256;
            const int c4  = idx >> 7;
            const int row = idx & 127;
            float4 av = *(const float4*)(A + (size_t)(bm + row) * K + k0 + c4 * 4);
            float4 wv = *(const float4*)(W + (size_t)(bn + row) * K + k0 + c4 * 4);
            As[c4 * 4 + 0][row] = to_tf32(av.x);
            As[c4 * 4 + 1][row] = to_tf32(av.y);
            As[c4 * 4 + 2][row] = to_tf32(av.z);
            As[c4 * 4 + 3][row] = to_tf32(av.w);
            Ws[c4 * 4 + 0][row] = to_tf32(wv.x);
            Ws[c4 * 4 + 1][row] = to_tf32(wv.y);
            Ws[c4 * 4 + 2][row] = to_tf32(wv.z);
            Ws[c4 * 4 + 3][row] = to_tf32(wv.w);
        }
        __syncthreads();

#pragma unroll
        for (int kk = 0; kk < 16; kk += 8) {
            uint32_t af[4][4];
#pragma unroll
            for (int i = 0; i < 4; i++) {
                const int mb = rb + i * 16 + gid;
                af[i][0] = __float_as_uint(As[kk + tig][mb]);
                af[i][1] = __float_as_uint(As[kk + tig][mb + 8]);
                af[i][2] = __float_as_uint(As[kk + tig + 4][mb]);
                af[i][3] = __float_as_uint(As[kk + tig + 4][mb + 8]);
            }
            uint32_t bf[4][2];
#pragma unroll
            for (int j = 0; j < 4; j++) {
                const int nc = nb + j * 8 + gid;
                bf[j][0] = __float_as_uint(Ws[kk + tig][nc]);
                bf[j][1] = __float_as_uint(Ws[kk + tig + 4][nc]);
            }
#pragma unroll
            for (int i = 0; i < 4; i++)
#pragma unroll
                for (int j = 0; j < 4; j++)
                    mma_tf32(c[i][j], af[i][0], af[i][1], af[i][2], af[i][3],
                             bf[j][0], bf[j][1]);
        }
        __syncthreads();
    }

    // epilogue: c0,c1 -> (row gid, cols tig*2, tig*2+1); c2,c3 -> row gid+8
#pragma unroll
    for (int i = 0; i < 4; i++) {
#pragma unroll
        for (int j = 0; j < 4; j++) {
            const int row = bm + rb + i * 16 + gid;
            const int col = bn + nb + j * 8 + tig * 2;
            *(float2*)(C + (size_t)row * N + col)       = make_float2(c[i][j][0], c[i][j][1]);
            *(float2*)(C + (size_t)(row + 8) * N + col) = make_float2(c[i][j][2], c[i][j][3]);
        }
    }
}

__global__ void __launch_bounds__(256) gemm_tf32(const float* __restrict__ A,
                                                 const float* __restrict__ W,
                                                 float* __restrict__ C,
                                                 int M, int N, int K) {
    gemm_tf32_body(A, W, C, M, N, K, blockIdx.y * 128, blockIdx.x * 128);
}

// Fused K+V projection: blockIdx.z selects (Wk -> g_k) or (Wv -> g_v).
__global__ void __launch_bounds__(256) gemm_tf32_kv(const float* __restrict__ A,
                                                    const float* __restrict__ Wk,
                                                    const float* __restrict__ Wv,
                                                    float* __restrict__ Ck,
                                                    float* __restrict__ Cv,
                                                    int M, int N, int K) {
    const float* W = (blockIdx.z == 0) ? Wk : Wv;
    float*       C = (blockIdx.z == 0) ? Ck : Cv;
    gemm_tf32_body(A, W, C, M, N, K, blockIdx.y * 128, blockIdx.x * 128);
}

// ---------------------------------------------------------------------------
// Fused per-head RMSNorm + RoPE, in place. One warp per (b,s,head) row of 64.
// ---------------------------------------------------------------------------
__global__ void __launch_bounds__(256) norm_rope(float* __restrict__ t,
                                                 const float* __restrict__ w,
                                                 const float* __restrict__ cosT,
                                                 const float* __restrict__ sinT,
                                                 int heads, int nrows) {
    const int warp = blockIdx.x * (blockDim.x >> 5) + (threadIdx.x >> 5);
    if (warp >= nrows) return;
    const int lane = threadIdx.x & 31;
    const int s = (warp / heads) % S_;

    float* row = t + (size_t)warp * HD_;
    float a = row[lane];
    float b = row[lane + 32];

    float ss = a * a + b * b;
#pragma unroll
    for (int o = 16; o > 0; o >>= 1) ss += __shfl_xor_sync(0xffffffffu, ss, o);

    const float r = rsqrtf(ss * (1.0f / 64.0f) + 1e-6f);
    const float n0 = a * r * w[lane];
    const float n1 = b * r * w[lane + 32];

    const float c0 = cosT[s * HD_ + lane];
    const float s0 = sinT[s * HD_ + lane];
    const float c1 = cosT[s * HD_ + lane + 32];
    const float s1 = sinT[s * HD_ + lane + 32];

    row[lane]      = n0 * c0 - n1 * s0;
    row[lane + 32] = n1 * c1 + n0 * s1;
}

// ---------------------------------------------------------------------------
// Causal flash attention, fp32. One thread per query row; BM=128 rows/CTA.
// ---------------------------------------------------------------------------
__global__ void __launch_bounds__(128) attn_kernel(const float* __restrict__ q,
                                                   const float* __restrict__ k,
                                                   const float* __restrict__ v,
                                                   float* __restrict__ o) {
    __shared__ float4 ksh[32][16];
    __shared__ float4 vsh[32][16];

    const int t  = threadIdx.x;
    const int b  = blockIdx.z;
    const int h  = blockIdx.y;
    const int kh = h >> 2;
    const int sq = blockIdx.x * 128 + t;

    const float* qrow = q + ((size_t)(b * S_ + sq) * H_ + h) * HD_;
    float qr[64];
#pragma unroll
    for (int d = 0; d < 64; d++) qr[d] = qrow[d] * 0.125f;

    float acc[64];
#pragma unroll
    for (int d = 0; d < 64; d++) acc[d] = 0.f;
    float m = -1e30f, l = 0.f;

    const int hi = blockIdx.x * 128 + 128;
    for (int n0 = 0; n0 < hi; n0 += 32) {
        const float* kbase = k + ((size_t)(b * S_ + n0) * KVH_ + kh) * HD_;
        const float* vbase = v + ((size_t)(b * S_ + n0) * KVH_ + kh) * HD_;
#pragma unroll
        for (int i = 0; i < 4; i++) {
            const int idx = t + i * 128;
            const int row = idx >> 4, c = idx & 15;
            ksh[row][c] = *(const float4*)(kbase + (size_t)row * (KVH_ * HD_) + c * 4);
            vsh[row][c] = *(const float4*)(vbase + (size_t)row * (KVH_ * HD_) + c * 4);
        }
        __syncthreads();

        float sc[32];
        float mt = -1e30f;
#pragma unroll
        for (int j = 0; j < 32; j++) {
            float s = 0.f;
#pragma unroll
            for (int c = 0; c < 16; c++) {
                float4 kv = ksh[j][c];
                s += qr[c * 4 + 0] * kv.x + qr[c * 4 + 1] * kv.y
                   + qr[c * 4 + 2] * kv.z + qr[c * 4 + 3] * kv.w;
            }
            if (n0 + j > sq) s = -1e30f;
            sc[j] = s;
            mt = fmaxf(mt, s);
        }

        const float mnew  = fmaxf(m, mt);
        const float alpha = exp2f((m - mnew) * 1.44269504f);
        l *= alpha;
#pragma unroll
        for (int d = 0; d < 64; d++) acc[d] *= alpha;

#pragma unroll
        for (int j = 0; j < 32; j++) {
            const float p = exp2f((sc[j] - mnew) * 1.44269504f);
            l += p;
#pragma unroll
            for (int c = 0; c < 16; c++) {
                float4 vv = vsh[j][c];
                acc[c * 4 + 0] += p * vv.x;  acc[c * 4 + 1] += p * vv.y;
                acc[c * 4 + 2] += p * vv.z;  acc[c * 4 + 3] += p * vv.w;
            }
        }
        m = mnew;
        __syncthreads();
    }

    const float inv = 1.f / l;
    float* orow = o + ((size_t)(b * S_ + sq) * H_ + h) * HD_;
#pragma unroll
    for (int d = 0; d < 64; d++) orow[d] = acc[d] * inv;
}

// ---------------------------------------------------------------------------
extern "C" void kernel_launch(void* const* d_in, const int* in_sizes, int n_in,
                              void* d_out, int out_size) {
    const float* x     = (const float*)d_in[0];
    // d_in[1] = mask (unused; causal hardcoded)
    const float* cosT  = (const float*)d_in[2];
    const float* sinT  = (const float*)d_in[3];
    const float* Wq    = (const float*)d_in[4];
    const float* Wk    = (const float*)d_in[5];
    const float* Wv    = (const float*)d_in[6];
    const float* Wo    = (const float*)d_in[7];
    const float* wqn   = (const float*)d_in[8];
    const float* wkn   = (const float*)d_in[9];
    float* out = (float*)d_out;

    float *q, *k, *v, *o;
    cudaGetSymbolAddress((void**)&q, g_q);
    cudaGetSymbolAddress((void**)&k, g_k);
    cudaGetSymbolAddress((void**)&v, g_v);
    cudaGetSymbolAddress((void**)&o, g_o);

    // Q projection (tf32 tensor cores)
    gemm_tf32<<<dim3((H_ * HD_) / 128, MROWS / 128), 256>>>(x, Wq, q, MROWS, H_ * HD_, DIN_);
    // K+V projections fused into one launch (z selects weight/output)
    gemm_tf32_kv<<<dim3((KVH_ * HD_) / 128, MROWS / 128, 2), 256>>>(x, Wk, Wv, k, v,
                                                                    MROWS, KVH_ * HD_, DIN_);

    // fused RMSNorm + RoPE on q and k
    {
        const int qrows = MROWS * H_;
        const int krows = MROWS * KVH_;
        norm_rope<<<(qrows + 7) / 8, 256>>>(q, wqn, cosT, sinT, H_, qrows);
        norm_rope<<<(krows + 7) / 8, 256>>>(k, wkn, cosT, sinT, KVH_, krows);
    }

    // causal GQA attention
    attn_kernel<<<dim3(S_ / 128, H_, B_), 128>>>(q, k, v, o);

    // output projection (tf32 tensor cores)
    gemm_tf32<<<dim3(DIN_ / 128, MROWS / 128), 256>>>(o, Wo, out, MROWS, DIN_, H_ * HD_);
}

// round 7
// speedup vs baseline: 2.7238x; 2.1768x over previous
#include <cuda_runtime.h>
#include <cuda_bf16.h>
#include <math.h>
#include <stdint.h>

#define B_    2
#define S_    2048
#define DIN_  2048
#define H_    32
#define KVH_  8
#define HD_   64
#define GROUPS_ 4
#define MROWS (B_ * S_)          // 4096
#define LOG2E 1.44269504f

// ---------------- scratch (static device arrays; no allocation) ------------
__device__ float g_q[(size_t)MROWS * H_   * HD_];   // [B,S,H,64]   32 MB
__device__ float g_k[(size_t)MROWS * KVH_ * HD_];   // [B,S,KVH,64]  8 MB
__device__ float g_v[(size_t)MROWS * KVH_ * HD_];   //               8 MB
__device__ float g_o[(size_t)MROWS * H_   * HD_];   // attn out     32 MB

// ---------------------------------------------------------------------------
// tf32 tensor-core GEMM (validated R5): C[M,N] = A[M,K] @ W[N,K]^T
// ---------------------------------------------------------------------------
__device__ __forceinline__ float to_tf32(float x) {
    float y;
    asm("cvt.rna.tf32.f32 %0, %1;" : "=f"(y) : "f"(x));
    return y;
}

__device__ __forceinline__ void mma_tf32(float c[4],
                                         uint32_t a0, uint32_t a1, uint32_t a2, uint32_t a3,
                                         uint32_t b0, uint32_t b1) {
    asm volatile(
        "mma.sync.aligned.m16n8k8.row.col.f32.tf32.tf32.f32 "
        "{%0,%1,%2,%3}, {%4,%5,%6,%7}, {%8,%9}, {%0,%1,%2,%3};"
        : "+f"(c[0]), "+f"(c[1]), "+f"(c[2]), "+f"(c[3])
        : "r"(a0), "r"(a1), "r"(a2), "r"(a3), "r"(b0), "r"(b1));
}

#define SST 136

__device__ __forceinline__ void gemm_tf32_body(const float* __restrict__ A,
                                               const float* __restrict__ W,
                                               float* __restrict__ C,
                                               int M, int N, int K,
                                               int bm, int bn) {
    __shared__ float As[16][SST];
    __shared__ float Ws[16][SST];

    const int tid  = threadIdx.x;
    const int lane = tid & 31;
    const int warp = tid >> 5;
    const int gid  = lane >> 2;
    const int tig  = lane & 3;

    const int warpM = warp & 1;
    const int warpN = warp >> 1;
    const int rb = warpM * 64;
    const int nb = warpN * 32;

    float c[4][4][4];
#pragma unroll
    for (int i = 0; i < 4; i++)
#pragma unroll
        for (int j = 0; j < 4; j++)
#pragma unroll
            for (int r = 0; r < 4; r++) c[i][j][r] = 0.f;

    for (int k0 = 0; k0 < K; k0 += 16) {
#pragma unroll
        for (int it = 0; it < 2; it++) {
            const int idx = tid + it * 256;
            const int c4  = idx >> 7;
            const int row = idx & 127;
            float4 av = *(const float4*)(A + (size_t)(bm + row) * K + k0 + c4 * 4);
            float4 wv = *(const float4*)(W + (size_t)(bn + row) * K + k0 + c4 * 4);
            As[c4 * 4 + 0][row] = to_tf32(av.x);
            As[c4 * 4 + 1][row] = to_tf32(av.y);
            As[c4 * 4 + 2][row] = to_tf32(av.z);
            As[c4 * 4 + 3][row] = to_tf32(av.w);
            Ws[c4 * 4 + 0][row] = to_tf32(wv.x);
            Ws[c4 * 4 + 1][row] = to_tf32(wv.y);
            Ws[c4 * 4 + 2][row] = to_tf32(wv.z);
            Ws[c4 * 4 + 3][row] = to_tf32(wv.w);
        }
        __syncthreads();

#pragma unroll
        for (int kk = 0; kk < 16; kk += 8) {
            uint32_t af[4][4];
#pragma unroll
            for (int i = 0; i < 4; i++) {
                const int mb = rb + i * 16 + gid;
                af[i][0] = __float_as_uint(As[kk + tig][mb]);
                af[i][1] = __float_as_uint(As[kk + tig][mb + 8]);
                af[i][2] = __float_as_uint(As[kk + tig + 4][mb]);
                af[i][3] = __float_as_uint(As[kk + tig + 4][mb + 8]);
            }
            uint32_t bf[4][2];
#pragma unroll
            for (int j = 0; j < 4; j++) {
                const int nc = nb + j * 8 + gid;
                bf[j][0] = __float_as_uint(Ws[kk + tig][nc]);
                bf[j][1] = __float_as_uint(Ws[kk + tig + 4][nc]);
            }
#pragma unroll
            for (int i = 0; i < 4; i++)
#pragma unroll
                for (int j = 0; j < 4; j++)
                    mma_tf32(c[i][j], af[i][0], af[i][1], af[i][2], af[i][3],
                             bf[j][0], bf[j][1]);
        }
        __syncthreads();
    }

#pragma unroll
    for (int i = 0; i < 4; i++) {
#pragma unroll
        for (int j = 0; j < 4; j++) {
            const int row = bm + rb + i * 16 + gid;
            const int col = bn + nb + j * 8 + tig * 2;
            *(float2*)(C + (size_t)row * N + col)       = make_float2(c[i][j][0], c[i][j][1]);
            *(float2*)(C + (size_t)(row + 8) * N + col) = make_float2(c[i][j][2], c[i][j][3]);
        }
    }
}

__global__ void __launch_bounds__(256) gemm_tf32(const float* __restrict__ A,
                                                 const float* __restrict__ W,
                                                 float* __restrict__ C,
                                                 int M, int N, int K) {
    gemm_tf32_body(A, W, C, M, N, K, blockIdx.y * 128, blockIdx.x * 128);
}

__global__ void __launch_bounds__(256) gemm_tf32_kv(const float* __restrict__ A,
                                                    const float* __restrict__ Wk,
                                                    const float* __restrict__ Wv,
                                                    float* __restrict__ Ck,
                                                    float* __restrict__ Cv,
                                                    int M, int N, int K) {
    const float* W = (blockIdx.z == 0) ? Wk : Wv;
    float*       C = (blockIdx.z == 0) ? Ck : Cv;
    gemm_tf32_body(A, W, C, M, N, K, blockIdx.y * 128, blockIdx.x * 128);
}

// ---------------------------------------------------------------------------
// Fused per-head RMSNorm + RoPE (validated)
// ---------------------------------------------------------------------------
__global__ void __launch_bounds__(256) norm_rope(float* __restrict__ t,
                                                 const float* __restrict__ w,
                                                 const float* __restrict__ cosT,
                                                 const float* __restrict__ sinT,
                                                 int heads, int nrows) {
    const int warp = blockIdx.x * (blockDim.x >> 5) + (threadIdx.x >> 5);
    if (warp >= nrows) return;
    const int lane = threadIdx.x & 31;
    const int s = (warp / heads) % S_;

    float* row = t + (size_t)warp * HD_;
    float a = row[lane];
    float b = row[lane + 32];

    float ss = a * a + b * b;
#pragma unroll
    for (int o = 16; o > 0; o >>= 1) ss += __shfl_xor_sync(0xffffffffu, ss, o);

    const float r = rsqrtf(ss * (1.0f / 64.0f) + 1e-6f);
    const float n0 = a * r * w[lane];
    const float n1 = b * r * w[lane + 32];

    const float c0 = cosT[s * HD_ + lane];
    const float s0 = sinT[s * HD_ + lane];
    const float c1 = cosT[s * HD_ + lane + 32];
    const float s1 = sinT[s * HD_ + lane + 32];

    row[lane]      = n0 * c0 - n1 * s0;
    row[lane + 32] = n1 * c1 + n0 * s1;
}

// ---------------------------------------------------------------------------
// bf16 helpers for split-precision tensor-core attention
// ---------------------------------------------------------------------------
__device__ __forceinline__ uint32_t packbf(float x0, float x1) {
    // low 16 bits <- x0 (lower k index), high 16 <- x1
    uint32_t r;
    asm("cvt.rn.bf16x2.f32 %0, %1, %2;" : "=r"(r) : "f"(x1), "f"(x0));
    return r;
}

// split x into hi (bf16) + lo (bf16 of residual); pack pairs
__device__ __forceinline__ void splitpack(float x0, float x1,
                                          uint32_t& hi, uint32_t& lo) {
    hi = packbf(x0, x1);
    __nv_bfloat162 hb = *(__nv_bfloat162*)&hi;
    lo = packbf(x0 - __bfloat162float(hb.x), x1 - __bfloat162float(hb.y));
}

__device__ __forceinline__ void mma_bf16(float c[4],
                                         const uint32_t a[4],
                                         uint32_t b0, uint32_t b1) {
    asm volatile(
        "mma.sync.aligned.m16n8k16.row.col.f32.bf16.bf16.f32 "
        "{%0,%1,%2,%3}, {%4,%5,%6,%7}, {%8,%9}, {%0,%1,%2,%3};"
        : "+f"(c[0]), "+f"(c[1]), "+f"(c[2]), "+f"(c[3])
        : "r"(a[0]), "r"(a[1]), "r"(a[2]), "r"(a[3]), "r"(b0), "r"(b1));
}

__device__ __forceinline__ void ldm4t(uint32_t r[4], uint32_t addr) {
    asm volatile(
        "ldmatrix.sync.aligned.m8n8.x4.trans.shared.b16 {%0,%1,%2,%3}, [%4];"
        : "=r"(r[0]), "=r"(r[1]), "=r"(r[2]), "=r"(r[3]) : "r"(addr));
}

// ---------------------------------------------------------------------------
// Tensor-core causal flash attention, split-bf16 (3-mma) precision.
// CTA: 64 q rows (4 warps x m16), key tiles of 32. Grid (S/64, H, B).
// ---------------------------------------------------------------------------
#define KVST 72   // smem stride (bf16 elems) for K/V tiles

__global__ void __launch_bounds__(128) attn_tc(const float* __restrict__ q,
                                               const float* __restrict__ k,
                                               const float* __restrict__ v,
                                               float* __restrict__ o) {
    __shared__ unsigned short ksh_hi[32][KVST], ksh_lo[32][KVST];
    __shared__ unsigned short vsh_hi[32][KVST], vsh_lo[32][KVST];

    const int t    = threadIdx.x;
    const int lane = t & 31;
    const int w    = t >> 5;
    const int gid  = lane >> 2;
    const int tig  = lane & 3;
    const int b    = blockIdx.z;
    const int h    = blockIdx.y;
    const int kh   = h >> 2;
    const int qb   = blockIdx.x * 64;
    const int r0   = qb + w * 16 + gid;     // rows for c0,c1 ; r0+8 for c2,c3

    // ---- Q fragments (split bf16, pre-scaled by HD^-0.5 = 0.125) ----
    uint32_t qh[4][4], ql[4][4];
    {
        const float* q0 = q + ((size_t)(b * S_ + r0) * H_ + h) * HD_;
        const float* q1 = q0 + (size_t)8 * H_ * HD_;
#pragma unroll
        for (int kc = 0; kc < 4; kc++) {
            const int d0 = kc * 16 + tig * 2;
            float2 x00 = *(const float2*)(q0 + d0);
            float2 x10 = *(const float2*)(q1 + d0);
            float2 x02 = *(const float2*)(q0 + d0 + 8);
            float2 x12 = *(const float2*)(q1 + d0 + 8);
            splitpack(x00.x * 0.125f, x00.y * 0.125f, qh[kc][0], ql[kc][0]);
            splitpack(x10.x * 0.125f, x10.y * 0.125f, qh[kc][1], ql[kc][1]);
            splitpack(x02.x * 0.125f, x02.y * 0.125f, qh[kc][2], ql[kc][2]);
            splitpack(x12.x * 0.125f, x12.y * 0.125f, qh[kc][3], ql[kc][3]);
        }
    }

    float oc[8][4];
#pragma unroll
    for (int nt = 0; nt < 8; nt++)
#pragma unroll
        for (int r = 0; r < 4; r++) oc[nt][r] = 0.f;
    float m0 = -1e30f, m1 = -1e30f, l0 = 0.f, l1 = 0.f;

    const uint32_t vhi_base = (uint32_t)__cvta_generic_to_shared(&vsh_hi[0][0]);
    const uint32_t vlo_base = (uint32_t)__cvta_generic_to_shared(&vsh_lo[0][0]);
    // ldmatrix lane address components (constant across tiles)
    const int lm_key = lane & 15;
    const int lm_d   = (lane >> 4) * 8;

    for (int n0 = 0; n0 < qb + 64; n0 += 32) {
        // ---- cooperative K/V tile load -> split bf16 smem ----
#pragma unroll
        for (int i = 0; i < 4; i++) {
            const int idx = t + i * 128;
            const int key = idx >> 4;
            const int c   = idx & 15;
            const size_t base = ((size_t)(b * S_ + n0 + key) * KVH_ + kh) * HD_ + c * 4;
            float4 kk = *(const float4*)(k + base);
            float4 vv = *(const float4*)(v + base);
            uint32_t h0, h1, lo0, lo1;
            splitpack(kk.x, kk.y, h0, lo0);
            splitpack(kk.z, kk.w, h1, lo1);
            *(uint2*)&ksh_hi[key][c * 4] = make_uint2(h0, h1);
            *(uint2*)&ksh_lo[key][c * 4] = make_uint2(lo0, lo1);
            splitpack(vv.x, vv.y, h0, lo0);
            splitpack(vv.z, vv.w, h1, lo1);
            *(uint2*)&vsh_hi[key][c * 4] = make_uint2(h0, h1);
            *(uint2*)&vsh_lo[key][c * 4] = make_uint2(lo0, lo1);
        }
        __syncthreads();

        const bool active = (n0 <= qb + w * 16 + 15);   // warp-uniform
        if (active) {
            // ---- S = Q K^T (3-mma split) ----
            float sc[4][4];
#pragma unroll
            for (int j = 0; j < 4; j++)
#pragma unroll
                for (int r = 0; r < 4; r++) sc[j][r] = 0.f;

#pragma unroll
            for (int j = 0; j < 4; j++) {
                const int key = j * 8 + gid;
#pragma unroll
                for (int kc = 0; kc < 4; kc++) {
                    const int d = kc * 16 + tig * 2;
                    uint32_t bh0 = *(const uint32_t*)&ksh_hi[key][d];
                    uint32_t bh1 = *(const uint32_t*)&ksh_hi[key][d + 8];
                    uint32_t bl0 = *(const uint32_t*)&ksh_lo[key][d];
                    uint32_t bl1 = *(const uint32_t*)&ksh_lo[key][d + 8];
                    mma_bf16(sc[j], qh[kc], bh0, bh1);
                    mma_bf16(sc[j], qh[kc], bl0, bl1);
                    mma_bf16(sc[j], ql[kc], bh0, bh1);
                }
            }

            // ---- causal mask (only near the diagonal; warp-uniform guard) ----
            if (n0 + 31 > qb + w * 16) {
#pragma unroll
                for (int j = 0; j < 4; j++) {
                    const int col = n0 + j * 8 + tig * 2;
                    if (col     > r0)     sc[j][0] = -1e30f;
                    if (col + 1 > r0)     sc[j][1] = -1e30f;
                    if (col     > r0 + 8) sc[j][2] = -1e30f;
                    if (col + 1 > r0 + 8) sc[j][3] = -1e30f;
                }
            }

            // ---- online softmax ----
            float tm0 = -1e30f, tm1 = -1e30f;
#pragma unroll
            for (int j = 0; j < 4; j++) {
                tm0 = fmaxf(tm0, fmaxf(sc[j][0], sc[j][1]));
                tm1 = fmaxf(tm1, fmaxf(sc[j][2], sc[j][3]));
            }
            tm0 = fmaxf(tm0, __shfl_xor_sync(0xffffffffu, tm0, 1));
            tm0 = fmaxf(tm0, __shfl_xor_sync(0xffffffffu, tm0, 2));
            tm1 = fmaxf(tm1, __shfl_xor_sync(0xffffffffu, tm1, 1));
            tm1 = fmaxf(tm1, __shfl_xor_sync(0xffffffffu, tm1, 2));

            const float mn0 = fmaxf(m0, tm0);
            const float mn1 = fmaxf(m1, tm1);
            const float al0 = exp2f((m0 - mn0) * LOG2E);
            const float al1 = exp2f((m1 - mn1) * LOG2E);
            m0 = mn0;  m1 = mn1;
            l0 *= al0; l1 *= al1;
#pragma unroll
            for (int nt = 0; nt < 8; nt++) {
                oc[nt][0] *= al0; oc[nt][1] *= al0;
                oc[nt][2] *= al1; oc[nt][3] *= al1;
            }
#pragma unroll
            for (int j = 0; j < 4; j++) {
                sc[j][0] = exp2f((sc[j][0] - mn0) * LOG2E);
                sc[j][1] = exp2f((sc[j][1] - mn0) * LOG2E);
                sc[j][2] = exp2f((sc[j][2] - mn1) * LOG2E);
                sc[j][3] = exp2f((sc[j][3] - mn1) * LOG2E);
                l0 += sc[j][0] + sc[j][1];
                l1 += sc[j][2] + sc[j][3];
            }

            // ---- O += P V (3-mma split); P repacked purely in registers ----
#pragma unroll
            for (int kc2 = 0; kc2 < 2; kc2++) {
                uint32_t pah[4], pal[4];
                splitpack(sc[2 * kc2][0],     sc[2 * kc2][1],     pah[0], pal[0]);
                splitpack(sc[2 * kc2][2],     sc[2 * kc2][3],     pah[1], pal[1]);
                splitpack(sc[2 * kc2 + 1][0], sc[2 * kc2 + 1][1], pah[2], pal[2]);
                splitpack(sc[2 * kc2 + 1][2], sc[2 * kc2 + 1][3], pah[3], pal[3]);
#pragma unroll
                for (int ntp = 0; ntp < 4; ntp++) {
                    const uint32_t off =
                        (uint32_t)(((kc2 * 16 + lm_key) * KVST + ntp * 16 + lm_d) * 2);
                    uint32_t vh[4], vl[4];
                    ldm4t(vh, vhi_base + off);
                    ldm4t(vl, vlo_base + off);
                    mma_bf16(oc[2 * ntp],     pah, vh[0], vh[1]);
                    mma_bf16(oc[2 * ntp],     pah, vl[0], vl[1]);
                    mma_bf16(oc[2 * ntp],     pal, vh[0], vh[1]);
                    mma_bf16(oc[2 * ntp + 1], pah, vh[2], vh[3]);
                    mma_bf16(oc[2 * ntp + 1], pah, vl[2], vl[3]);
                    mma_bf16(oc[2 * ntp + 1], pal, vh[2], vh[3]);
                }
            }
        }
        __syncthreads();
    }

    // ---- final row-sum reduce + write ----
    l0 += __shfl_xor_sync(0xffffffffu, l0, 1);
    l0 += __shfl_xor_sync(0xffffffffu, l0, 2);
    l1 += __shfl_xor_sync(0xffffffffu, l1, 1);
    l1 += __shfl_xor_sync(0xffffffffu, l1, 2);
    const float inv0 = 1.f / l0;
    const float inv1 = 1.f / l1;

    float* o0 = o + ((size_t)(b * S_ + r0) * H_ + h) * HD_;
    float* o1 = o0 + (size_t)8 * H_ * HD_;
#pragma unroll
    for (int nt = 0; nt < 8; nt++) {
        *(float2*)(o0 + nt * 8 + tig * 2) =
            make_float2(oc[nt][0] * inv0, oc[nt][1] * inv0);
        *(float2*)(o1 + nt * 8 + tig * 2) =
            make_float2(oc[nt][2] * inv1, oc[nt][3] * inv1);
    }
}

// ---------------------------------------------------------------------------
extern "C" void kernel_launch(void* const* d_in, const int* in_sizes, int n_in,
                              void* d_out, int out_size) {
    const float* x     = (const float*)d_in[0];
    // d_in[1] = mask (unused; causal hardcoded)
    const float* cosT  = (const float*)d_in[2];
    const float* sinT  = (const float*)d_in[3];
    const float* Wq    = (const float*)d_in[4];
    const float* Wk    = (const float*)d_in[5];
    const float* Wv    = (const float*)d_in[6];
    const float* Wo    = (const float*)d_in[7];
    const float* wqn   = (const float*)d_in[8];
    const float* wkn   = (const float*)d_in[9];
    float* out = (float*)d_out;

    float *q, *k, *v, *o;
    cudaGetSymbolAddress((void**)&q, g_q);
    cudaGetSymbolAddress((void**)&k, g_k);
    cudaGetSymbolAddress((void**)&v, g_v);
    cudaGetSymbolAddress((void**)&o, g_o);

    // Q projection (tf32 tensor cores)
    gemm_tf32<<<dim3((H_ * HD_) / 128, MROWS / 128), 256>>>(x, Wq, q, MROWS, H_ * HD_, DIN_);
    // K+V projections fused into one launch
    gemm_tf32_kv<<<dim3((KVH_ * HD_) / 128, MROWS / 128, 2), 256>>>(x, Wk, Wv, k, v,
                                                                    MROWS, KVH_ * HD_, DIN_);

    // fused RMSNorm + RoPE on q and k
    {
        const int qrows = MROWS * H_;
        const int krows = MROWS * KVH_;
        norm_rope<<<(qrows + 7) / 8, 256>>>(q, wqn, cosT, sinT, H_, qrows);
        norm_rope<<<(krows + 7) / 8, 256>>>(k, wkn, cosT, sinT, KVH_, krows);
    }

    // causal GQA attention (tensor cores, split-bf16)
    attn_tc<<<dim3(S_ / 64, H_, B_), 128>>>(q, k, v, o);

    // output projection (tf32 tensor cores)
    gemm_tf32<<<dim3(DIN_ / 128, MROWS / 128), 256>>>(o, Wo, out, MROWS, DIN_, H_ * HD_);
}

// round 8
// speedup vs baseline: 2.7565x; 1.0120x over previous
#include <cuda_runtime.h>
#include <cuda_bf16.h>
#include <math.h>
#include <stdint.h>

#define B_    2
#define S_    2048
#define DIN_  2048
#define H_    32
#define KVH_  8
#define HD_   64
#define GROUPS_ 4
#define MROWS (B_ * S_)          // 4096
#define LOG2E 1.44269504f

// ---------------- scratch (static device arrays; no allocation) ------------
__device__ float g_q[(size_t)MROWS * H_   * HD_];   // [B,S,H,64]   32 MB
__device__ float g_k[(size_t)MROWS * KVH_ * HD_];   // [B,S,KVH,64]  8 MB
__device__ float g_v[(size_t)MROWS * KVH_ * HD_];   //               8 MB
__device__ float g_o[(size_t)MROWS * H_   * HD_];   // attn out     32 MB

// ---------------------------------------------------------------------------
// tf32 tensor-core GEMM, double-buffered: C[M,N] = A[M,K] @ W[N,K]^T
// BM=BN=128, BK=16, 256 threads (8 warps), warp tile 64x32 of m16n8k8 mmas.
// ---------------------------------------------------------------------------
__device__ __forceinline__ float to_tf32(float x) {
    float y;
    asm("cvt.rna.tf32.f32 %0, %1;" : "=f"(y) : "f"(x));
    return y;
}

__device__ __forceinline__ void mma_tf32(float c[4],
                                         uint32_t a0, uint32_t a1, uint32_t a2, uint32_t a3,
                                         uint32_t b0, uint32_t b1) {
    asm volatile(
        "mma.sync.aligned.m16n8k8.row.col.f32.tf32.tf32.f32 "
        "{%0,%1,%2,%3}, {%4,%5,%6,%7}, {%8,%9}, {%0,%1,%2,%3};"
        : "+f"(c[0]), "+f"(c[1]), "+f"(c[2]), "+f"(c[3])
        : "r"(a0), "r"(a1), "r"(a2), "r"(a3), "r"(b0), "r"(b1));
}

#define SST 136   // (k*SST + m) % 32 == (k*8 + m) % 32 -> conflict-free frag LDS

__device__ __forceinline__ void gemm_tf32_body(const float* __restrict__ A,
                                               const float* __restrict__ W,
                                               float* __restrict__ C,
                                               int M, int N, int K,
                                               int bm, int bn) {
    __shared__ float As[2][16][SST];
    __shared__ float Ws[2][16][SST];

    const int tid  = threadIdx.x;
    const int lane = tid & 31;
    const int warp = tid >> 5;
    const int gid  = lane >> 2;
    const int tig  = lane & 3;

    const int warpM = warp & 1;
    const int warpN = warp >> 1;
    const int rb = warpM * 64;
    const int nb = warpN * 32;

    // loader mapping: row = tid&127 (same for both chunks), k-chunks c4a and c4a+2
    const int row = tid & 127;
    const int c4a = tid >> 7;                 // 0..1
    const float* pA = A + (size_t)(bm + row) * K + c4a * 4;
    const float* pW = W + (size_t)(bn + row) * K + c4a * 4;

    float c[4][4][4];
#pragma unroll
    for (int i = 0; i < 4; i++)
#pragma unroll
        for (int j = 0; j < 4; j++)
#pragma unroll
            for (int r = 0; r < 4; r++) c[i][j][r] = 0.f;

    // prefetch first chunk
    float4 pa0 = *(const float4*)(pA);
    float4 pa1 = *(const float4*)(pA + 8);
    float4 pw0 = *(const float4*)(pW);
    float4 pw1 = *(const float4*)(pW + 8);

    int buf = 0;
    for (int k0 = 0; k0 < K; k0 += 16) {
        // store prefetched chunk (tf32-converted) into smem[buf]
        As[buf][c4a * 4 + 0][row] = to_tf32(pa0.x);
        As[buf][c4a * 4 + 1][row] = to_tf32(pa0.y);
        As[buf][c4a * 4 + 2][row] = to_tf32(pa0.z);
        As[buf][c4a * 4 + 3][row] = to_tf32(pa0.w);
        As[buf][c4a * 4 + 8][row] = to_tf32(pa1.x);
        As[buf][c4a * 4 + 9][row] = to_tf32(pa1.y);
        As[buf][c4a * 4 + 10][row] = to_tf32(pa1.z);
        As[buf][c4a * 4 + 11][row] = to_tf32(pa1.w);
        Ws[buf][c4a * 4 + 0][row] = to_tf32(pw0.x);
        Ws[buf][c4a * 4 + 1][row] = to_tf32(pw0.y);
        Ws[buf][c4a * 4 + 2][row] = to_tf32(pw0.z);
        Ws[buf][c4a * 4 + 3][row] = to_tf32(pw0.w);
        Ws[buf][c4a * 4 + 8][row] = to_tf32(pw1.x);
        Ws[buf][c4a * 4 + 9][row] = to_tf32(pw1.y);
        Ws[buf][c4a * 4 + 10][row] = to_tf32(pw1.z);
        Ws[buf][c4a * 4 + 11][row] = to_tf32(pw1.w);
        __syncthreads();

        // issue next chunk's global loads (overlap with compute below)
        if (k0 + 16 < K) {
            pa0 = *(const float4*)(pA + k0 + 16);
            pa1 = *(const float4*)(pA + k0 + 24);
            pw0 = *(const float4*)(pW + k0 + 16);
            pw1 = *(const float4*)(pW + k0 + 24);
        }

#pragma unroll
        for (int kk = 0; kk < 16; kk += 8) {
            uint32_t af[4][4];
#pragma unroll
            for (int i = 0; i < 4; i++) {
                const int mb = rb + i * 16 + gid;
                af[i][0] = __float_as_uint(As[buf][kk + tig][mb]);
                af[i][1] = __float_as_uint(As[buf][kk + tig][mb + 8]);
                af[i][2] = __float_as_uint(As[buf][kk + tig + 4][mb]);
                af[i][3] = __float_as_uint(As[buf][kk + tig + 4][mb + 8]);
            }
            uint32_t bf[4][2];
#pragma unroll
            for (int j = 0; j < 4; j++) {
                const int nc = nb + j * 8 + gid;
                bf[j][0] = __float_as_uint(Ws[buf][kk + tig][nc]);
                bf[j][1] = __float_as_uint(Ws[buf][kk + tig + 4][nc]);
            }
#pragma unroll
            for (int i = 0; i < 4; i++)
#pragma unroll
                for (int j = 0; j < 4; j++)
                    mma_tf32(c[i][j], af[i][0], af[i][1], af[i][2], af[i][3],
                             bf[j][0], bf[j][1]);
        }
        buf ^= 1;   // no trailing sync needed: next write to this buf is
                    // separated from these reads by the next iteration's barrier
    }

#pragma unroll
    for (int i = 0; i < 4; i++) {
#pragma unroll
        for (int j = 0; j < 4; j++) {
            const int orow = bm + rb + i * 16 + gid;
            const int ocol = bn + nb + j * 8 + tig * 2;
            *(float2*)(C + (size_t)orow * N + ocol)       = make_float2(c[i][j][0], c[i][j][1]);
            *(float2*)(C + (size_t)(orow + 8) * N + ocol) = make_float2(c[i][j][2], c[i][j][3]);
        }
    }
}

__global__ void __launch_bounds__(256, 2) gemm_tf32(const float* __restrict__ A,
                                                    const float* __restrict__ W,
                                                    float* __restrict__ C,
                                                    int M, int N, int K) {
    gemm_tf32_body(A, W, C, M, N, K, blockIdx.y * 128, blockIdx.x * 128);
}

__global__ void __launch_bounds__(256, 2) gemm_tf32_kv(const float* __restrict__ A,
                                                       const float* __restrict__ Wk,
                                                       const float* __restrict__ Wv,
                                                       float* __restrict__ Ck,
                                                       float* __restrict__ Cv,
                                                       int M, int N, int K) {
    const float* W = (blockIdx.z == 0) ? Wk : Wv;
    float*       C = (blockIdx.z == 0) ? Ck : Cv;
    gemm_tf32_body(A, W, C, M, N, K, blockIdx.y * 128, blockIdx.x * 128);
}

// ---------------------------------------------------------------------------
// Fused per-head RMSNorm + RoPE (validated)
// ---------------------------------------------------------------------------
__global__ void __launch_bounds__(256) norm_rope(float* __restrict__ t,
                                                 const float* __restrict__ w,
                                                 const float* __restrict__ cosT,
                                                 const float* __restrict__ sinT,
                                                 int heads, int nrows) {
    const int warp = blockIdx.x * (blockDim.x >> 5) + (threadIdx.x >> 5);
    if (warp >= nrows) return;
    const int lane = threadIdx.x & 31;
    const int s = (warp / heads) % S_;

    float* row = t + (size_t)warp * HD_;
    float a = row[lane];
    float b = row[lane + 32];

    float ss = a * a + b * b;
#pragma unroll
    for (int o = 16; o > 0; o >>= 1) ss += __shfl_xor_sync(0xffffffffu, ss, o);

    const float r = rsqrtf(ss * (1.0f / 64.0f) + 1e-6f);
    const float n0 = a * r * w[lane];
    const float n1 = b * r * w[lane + 32];

    const float c0 = cosT[s * HD_ + lane];
    const float s0 = sinT[s * HD_ + lane];
    const float c1 = cosT[s * HD_ + lane + 32];
    const float s1 = sinT[s * HD_ + lane + 32];

    row[lane]      = n0 * c0 - n1 * s0;
    row[lane + 32] = n1 * c1 + n0 * s1;
}

// ---------------------------------------------------------------------------
// bf16 helpers for split-precision tensor-core attention
// ---------------------------------------------------------------------------
__device__ __forceinline__ uint32_t packbf(float x0, float x1) {
    uint32_t r;
    asm("cvt.rn.bf16x2.f32 %0, %1, %2;" : "=r"(r) : "f"(x1), "f"(x0));
    return r;
}

__device__ __forceinline__ void splitpack(float x0, float x1,
                                          uint32_t& hi, uint32_t& lo) {
    hi = packbf(x0, x1);
    __nv_bfloat162 hb = *(__nv_bfloat162*)&hi;
    lo = packbf(x0 - __bfloat162float(hb.x), x1 - __bfloat162float(hb.y));
}

__device__ __forceinline__ void mma_bf16(float c[4],
                                         const uint32_t a[4],
                                         uint32_t b0, uint32_t b1) {
    asm volatile(
        "mma.sync.aligned.m16n8k16.row.col.f32.bf16.bf16.f32 "
        "{%0,%1,%2,%3}, {%4,%5,%6,%7}, {%8,%9}, {%0,%1,%2,%3};"
        : "+f"(c[0]), "+f"(c[1]), "+f"(c[2]), "+f"(c[3])
        : "r"(a[0]), "r"(a[1]), "r"(a[2]), "r"(a[3]), "r"(b0), "r"(b1));
}

__device__ __forceinline__ void ldm4t(uint32_t r[4], uint32_t addr) {
    asm volatile(
        "ldmatrix.sync.aligned.m8n8.x4.trans.shared.b16 {%0,%1,%2,%3}, [%4];"
        : "=r"(r[0]), "=r"(r[1]), "=r"(r[2]), "=r"(r[3]) : "r"(addr));
}

// ---------------------------------------------------------------------------
// Tensor-core causal flash attention, split-bf16 (3-mma) precision.
// CTA: 64 q rows (4 warps x m16), key tiles of 32. Grid (S/64, H, B).
// ---------------------------------------------------------------------------
#define KVST 72

__global__ void __launch_bounds__(128) attn_tc(const float* __restrict__ q,
                                               const float* __restrict__ k,
                                               const float* __restrict__ v,
                                               float* __restrict__ o) {
    __shared__ unsigned short ksh_hi[32][KVST], ksh_lo[32][KVST];
    __shared__ unsigned short vsh_hi[32][KVST], vsh_lo[32][KVST];

    const int t    = threadIdx.x;
    const int lane = t & 31;
    const int w    = t >> 5;
    const int gid  = lane >> 2;
    const int tig  = lane & 3;
    const int b    = blockIdx.z;
    const int h    = blockIdx.y;
    const int kh   = h >> 2;
    const int qb   = blockIdx.x * 64;
    const int r0   = qb + w * 16 + gid;

    uint32_t qh[4][4], ql[4][4];
    {
        const float* q0 = q + ((size_t)(b * S_ + r0) * H_ + h) * HD_;
        const float* q1 = q0 + (size_t)8 * H_ * HD_;
#pragma unroll
        for (int kc = 0; kc < 4; kc++) {
            const int d0 = kc * 16 + tig * 2;
            float2 x00 = *(const float2*)(q0 + d0);
            float2 x10 = *(const float2*)(q1 + d0);
            float2 x02 = *(const float2*)(q0 + d0 + 8);
            float2 x12 = *(const float2*)(q1 + d0 + 8);
            splitpack(x00.x * 0.125f, x00.y * 0.125f, qh[kc][0], ql[kc][0]);
            splitpack(x10.x * 0.125f, x10.y * 0.125f, qh[kc][1], ql[kc][1]);
            splitpack(x02.x * 0.125f, x02.y * 0.125f, qh[kc][2], ql[kc][2]);
            splitpack(x12.x * 0.125f, x12.y * 0.125f, qh[kc][3], ql[kc][3]);
        }
    }

    float oc[8][4];
#pragma unroll
    for (int nt = 0; nt < 8; nt++)
#pragma unroll
        for (int r = 0; r < 4; r++) oc[nt][r] = 0.f;
    float m0 = -1e30f, m1 = -1e30f, l0 = 0.f, l1 = 0.f;

    const uint32_t vhi_base = (uint32_t)__cvta_generic_to_shared(&vsh_hi[0][0]);
    const uint32_t vlo_base = (uint32_t)__cvta_generic_to_shared(&vsh_lo[0][0]);
    const int lm_key = lane & 15;
    const int lm_d   = (lane >> 4) * 8;

    for (int n0 = 0; n0 < qb + 64; n0 += 32) {
#pragma unroll
        for (int i = 0; i < 4; i++) {
            const int idx = t + i * 128;
            const int key = idx >> 4;
            const int c   = idx & 15;
            const size_t base = ((size_t)(b * S_ + n0 + key) * KVH_ + kh) * HD_ + c * 4;
            float4 kk = *(const float4*)(k + base);
            float4 vv = *(const float4*)(v + base);
            uint32_t h0, h1, lo0, lo1;
            splitpack(kk.x, kk.y, h0, lo0);
            splitpack(kk.z, kk.w, h1, lo1);
            *(uint2*)&ksh_hi[key][c * 4] = make_uint2(h0, h1);
            *(uint2*)&ksh_lo[key][c * 4] = make_uint2(lo0, lo1);
            splitpack(vv.x, vv.y, h0, lo0);
            splitpack(vv.z, vv.w, h1, lo1);
            *(uint2*)&vsh_hi[key][c * 4] = make_uint2(h0, h1);
            *(uint2*)&vsh_lo[key][c * 4] = make_uint2(lo0, lo1);
        }
        __syncthreads();

        const bool active = (n0 <= qb + w * 16 + 15);
        if (active) {
            float sc[4][4];
#pragma unroll
            for (int j = 0; j < 4; j++)
#pragma unroll
                for (int r = 0; r < 4; r++) sc[j][r] = 0.f;

#pragma unroll
            for (int j = 0; j < 4; j++) {
                const int key = j * 8 + gid;
#pragma unroll
                for (int kc = 0; kc < 4; kc++) {
                    const int d = kc * 16 + tig * 2;
                    uint32_t bh0 = *(const uint32_t*)&ksh_hi[key][d];
                    uint32_t bh1 = *(const uint32_t*)&ksh_hi[key][d + 8];
                    uint32_t bl0 = *(const uint32_t*)&ksh_lo[key][d];
                    uint32_t bl1 = *(const uint32_t*)&ksh_lo[key][d + 8];
                    mma_bf16(sc[j], qh[kc], bh0, bh1);
                    mma_bf16(sc[j], qh[kc], bl0, bl1);
                    mma_bf16(sc[j], ql[kc], bh0, bh1);
                }
            }

            if (n0 + 31 > qb + w * 16) {
#pragma unroll
                for (int j = 0; j < 4; j++) {
                    const int col = n0 + j * 8 + tig * 2;
                    if (col     > r0)     sc[j][0] = -1e30f;
                    if (col + 1 > r0)     sc[j][1] = -1e30f;
                    if (col     > r0 + 8) sc[j][2] = -1e30f;
                    if (col + 1 > r0 + 8) sc[j][3] = -1e30f;
                }
            }

            float tm0 = -1e30f, tm1 = -1e30f;
#pragma unroll
            for (int j = 0; j < 4; j++) {
                tm0 = fmaxf(tm0, fmaxf(sc[j][0], sc[j][1]));
                tm1 = fmaxf(tm1, fmaxf(sc[j][2], sc[j][3]));
            }
            tm0 = fmaxf(tm0, __shfl_xor_sync(0xffffffffu, tm0, 1));
            tm0 = fmaxf(tm0, __shfl_xor_sync(0xffffffffu, tm0, 2));
            tm1 = fmaxf(tm1, __shfl_xor_sync(0xffffffffu, tm1, 1));
            tm1 = fmaxf(tm1, __shfl_xor_sync(0xffffffffu, tm1, 2));

            const float mn0 = fmaxf(m0, tm0);
            const float mn1 = fmaxf(m1, tm1);
            const float al0 = exp2f((m0 - mn0) * LOG2E);
            const float al1 = exp2f((m1 - mn1) * LOG2E);
            m0 = mn0;  m1 = mn1;
            l0 *= al0; l1 *= al1;
#pragma unroll
            for (int nt = 0; nt < 8; nt++) {
                oc[nt][0] *= al0; oc[nt][1] *= al0;
                oc[nt][2] *= al1; oc[nt][3] *= al1;
            }
#pragma unroll
            for (int j = 0; j < 4; j++) {
                sc[j][0] = exp2f((sc[j][0] - mn0) * LOG2E);
                sc[j][1] = exp2f((sc[j][1] - mn0) * LOG2E);
                sc[j][2] = exp2f((sc[j][2] - mn1) * LOG2E);
                sc[j][3] = exp2f((sc[j][3] - mn1) * LOG2E);
                l0 += sc[j][0] + sc[j][1];
                l1 += sc[j][2] + sc[j][3];
            }

#pragma unroll
            for (int kc2 = 0; kc2 < 2; kc2++) {
                uint32_t pah[4], pal[4];
                splitpack(sc[2 * kc2][0],     sc[2 * kc2][1],     pah[0], pal[0]);
                splitpack(sc[2 * kc2][2],     sc[2 * kc2][3],     pah[1], pal[1]);
                splitpack(sc[2 * kc2 + 1][0], sc[2 * kc2 + 1][1], pah[2], pal[2]);
                splitpack(sc[2 * kc2 + 1][2], sc[2 * kc2 + 1][3], pah[3], pal[3]);
#pragma unroll
                for (int ntp = 0; ntp < 4; ntp++) {
                    const uint32_t off =
                        (uint32_t)(((kc2 * 16 + lm_key) * KVST + ntp * 16 + lm_d) * 2);
                    uint32_t vh[4], vl[4];
                    ldm4t(vh, vhi_base + off);
                    ldm4t(vl, vlo_base + off);
                    mma_bf16(oc[2 * ntp],     pah, vh[0], vh[1]);
                    mma_bf16(oc[2 * ntp],     pah, vl[0], vl[1]);
                    mma_bf16(oc[2 * ntp],     pal, vh[0], vh[1]);
                    mma_bf16(oc[2 * ntp + 1], pah, vh[2], vh[3]);
                    mma_bf16(oc[2 * ntp + 1], pah, vl[2], vl[3]);
                    mma_bf16(oc[2 * ntp + 1], pal, vh[2], vh[3]);
                }
            }
        }
        __syncthreads();
    }

    l0 += __shfl_xor_sync(0xffffffffu, l0, 1);
    l0 += __shfl_xor_sync(0xffffffffu, l0, 2);
    l1 += __shfl_xor_sync(0xffffffffu, l1, 1);
    l1 += __shfl_xor_sync(0xffffffffu, l1, 2);
    const float inv0 = 1.f / l0;
    const float inv1 = 1.f / l1;

    float* o0 = o + ((size_t)(b * S_ + r0) * H_ + h) * HD_;
    float* o1 = o0 + (size_t)8 * H_ * HD_;
#pragma unroll
    for (int nt = 0; nt < 8; nt++) {
        *(float2*)(o0 + nt * 8 + tig * 2) =
            make_float2(oc[nt][0] * inv0, oc[nt][1] * inv0);
        *(float2*)(o1 + nt * 8 + tig * 2) =
            make_float2(oc[nt][2] * inv1, oc[nt][3] * inv1);
    }
}

// ---------------------------------------------------------------------------
extern "C" void kernel_launch(void* const* d_in, const int* in_sizes, int n_in,
                              void* d_out, int out_size) {
    const float* x     = (const float*)d_in[0];
    // d_in[1] = mask (unused; causal hardcoded)
    const float* cosT  = (const float*)d_in[2];
    const float* sinT  = (const float*)d_in[3];
    const float* Wq    = (const float*)d_in[4];
    const float* Wk    = (const float*)d_in[5];
    const float* Wv    = (const float*)d_in[6];
    const float* Wo    = (const float*)d_in[7];
    const float* wqn   = (const float*)d_in[8];
    const float* wkn   = (const float*)d_in[9];
    float* out = (float*)d_out;

    float *q, *k, *v, *o;
    cudaGetSymbolAddress((void**)&q, g_q);
    cudaGetSymbolAddress((void**)&k, g_k);
    cudaGetSymbolAddress((void**)&v, g_v);
    cudaGetSymbolAddress((void**)&o, g_o);

    // Q projection (tf32 tensor cores, double-buffered)
    gemm_tf32<<<dim3((H_ * HD_) / 128, MROWS / 128), 256>>>(x, Wq, q, MROWS, H_ * HD_, DIN_);
    // K+V projections fused into one launch
    gemm_tf32_kv<<<dim3((KVH_ * HD_) / 128, MROWS / 128, 2), 256>>>(x, Wk, Wv, k, v,
                                                                    MROWS, KVH_ * HD_, DIN_);

    // fused RMSNorm + RoPE on q and k
    {
        const int qrows = MROWS * H_;
        const int krows = MROWS * KVH_;
        norm_rope<<<(qrows + 7) / 8, 256>>>(q, wqn, cosT, sinT, H_, qrows);
        norm_rope<<<(krows + 7) / 8, 256>>>(k, wkn, cosT, sinT, KVH_, krows);
    }

    // causal GQA attention (tensor cores, split-bf16)
    attn_tc<<<dim3(S_ / 64, H_, B_), 128>>>(q, k, v, o);

    // output projection (tf32 tensor cores, double-buffered)
    gemm_tf32<<<dim3(DIN_ / 128, MROWS / 128), 256>>>(o, Wo, out, MROWS, DIN_, H_ * HD_);
}

// round 11
// speedup vs baseline: 4.1063x; 1.4897x over previous
#include <cuda_runtime.h>
#include <cuda_bf16.h>
#include <math.h>
#include <stdint.h>

#define B_    2
#define S_    2048
#define DIN_  2048
#define H_    32
#define KVH_  8
#define HD_   64
#define MROWS (B_ * S_)          // 4096
#define LOG2E 1.44269504f
#define GK    2048               // K dim of all projections

// ---------------- scratch (static device arrays; no allocation) ------------
__device__ float g_q[(size_t)MROWS * H_   * HD_];
__device__ float g_k[(size_t)MROWS * KVH_ * HD_];
__device__ float g_v[(size_t)MROWS * KVH_ * HD_];
__device__ float g_o[(size_t)MROWS * H_   * HD_];

// ---------------------------------------------------------------------------
// helpers
// ---------------------------------------------------------------------------
__device__ __forceinline__ float to_tf32(float x) {
    float y;
    asm("cvt.rna.tf32.f32 %0, %1;" : "=f"(y) : "f"(x));
    return y;
}
__device__ __forceinline__ void mma_tf32(float c[4],
                                         const uint32_t a[4],
                                         uint32_t b0, uint32_t b1) {
    asm volatile(
        "mma.sync.aligned.m16n8k8.row.col.f32.tf32.tf32.f32 "
        "{%0,%1,%2,%3}, {%4,%5,%6,%7}, {%8,%9}, {%0,%1,%2,%3};"
        : "+f"(c[0]), "+f"(c[1]), "+f"(c[2]), "+f"(c[3])
        : "r"(a[0]), "r"(a[1]), "r"(a[2]), "r"(a[3]), "r"(b0), "r"(b1));
}
__device__ __forceinline__ void ldm4(uint32_t r[4], uint32_t addr) {
    asm volatile(
        "ldmatrix.sync.aligned.m8n8.x4.shared.b16 {%0,%1,%2,%3}, [%4];"
        : "=r"(r[0]), "=r"(r[1]), "=r"(r[2]), "=r"(r[3]) : "r"(addr));
}
__device__ __forceinline__ uint32_t smem_u32(const void* p) {
    return (uint32_t)__cvta_generic_to_shared(p);
}

// ---------------------------------------------------------------------------
// tf32 GEMM via mma.sync + ldmatrix fragments.
// C[M,N] = A[M,K] @ W[N,K]^T. BM=BN=128, BK=32, 256 thr, warp tile 64x32.
// Smem layout [m][k] stride 36 floats (144B): conflict-free STS.128 + ldmatrix.
// ---------------------------------------------------------------------------
#define AST   36
#define BUFSZ (128 * AST)        // floats per tile buffer

__device__ __forceinline__ void gemm_tf32_body(const float* __restrict__ A,
                                               const float* __restrict__ W,
                                               float* __restrict__ C,
                                               int N, int bm, int bn) {
    extern __shared__ float sm[];
    float* AsBase = sm;                  // [2][BUFSZ]
    float* WsBase = sm + 2 * BUFSZ;      // [2][BUFSZ]

    const int tid  = threadIdx.x;
    const int lane = tid & 31;
    const int warp = tid >> 5;
    const int gid  = lane >> 2;
    const int tig  = lane & 3;

    const int rb = (warp & 1) * 64;      // warp row base
    const int nb = (warp >> 1) * 32;     // warp col base

    // loader mapping: 2 threads per row, each loads 16 consecutive floats
    const int lrow = tid >> 1;
    const int col0 = (tid & 1) * 16;
    const float* pA = A + (size_t)(bm + lrow) * GK + col0;
    const float* pW = W + (size_t)(bn + lrow) * GK + col0;

    // ldmatrix per-lane address offsets (in floats)
    const int g    = lane >> 3;
    const int grow = lane & 7;
    int a_off[4], b_off[2];
#pragma unroll
    for (int i = 0; i < 4; i++)
        a_off[i] = (rb + i * 16 + (g & 1) * 8 + grow) * AST + (g >> 1) * 4;
#pragma unroll
    for (int jj = 0; jj < 2; jj++)
        b_off[jj] = (nb + (jj * 2 + (g >> 1)) * 8 + grow) * AST + (g & 1) * 4;

    const uint32_t a_smem = smem_u32(AsBase);
    const uint32_t w_smem = smem_u32(WsBase);

    float c[4][4][4];
#pragma unroll
    for (int i = 0; i < 4; i++)
#pragma unroll
        for (int j = 0; j < 4; j++)
#pragma unroll
            for (int r = 0; r < 4; r++) c[i][j][r] = 0.f;

    // prefetch first chunk (4 float4 each from A and W)
    float4 pa[4], pw[4];
#pragma unroll
    for (int i = 0; i < 4; i++) {
        pa[i] = *(const float4*)(pA + i * 4);
        pw[i] = *(const float4*)(pW + i * 4);
    }

    int buf = 0;
    for (int k0 = 0; k0 < GK; k0 += 32) {
        // store prefetched chunk (tf32-rounded)
        float* dA = AsBase + buf * BUFSZ + lrow * AST + col0;
        float* dW = WsBase + buf * BUFSZ + lrow * AST + col0;
#pragma unroll
        for (int i = 0; i < 4; i++) {
            *(float4*)(dA + i * 4) = make_float4(to_tf32(pa[i].x), to_tf32(pa[i].y),
                                                 to_tf32(pa[i].z), to_tf32(pa[i].w));
            *(float4*)(dW + i * 4) = make_float4(to_tf32(pw[i].x), to_tf32(pw[i].y),
                                                 to_tf32(pw[i].z), to_tf32(pw[i].w));
        }
        __syncthreads();

        // issue next chunk's global loads (overlap with mma below)
        if (k0 + 32 < GK) {
#pragma unroll
            for (int i = 0; i < 4; i++) {
                pa[i] = *(const float4*)(pA + k0 + 32 + i * 4);
                pw[i] = *(const float4*)(pW + k0 + 32 + i * 4);
            }
        }

        const uint32_t ab = a_smem + buf * (BUFSZ * 4);
        const uint32_t wb = w_smem + buf * (BUFSZ * 4);
#pragma unroll
        for (int kk = 0; kk < 32; kk += 8) {
            uint32_t af[4][4];
#pragma unroll
            for (int i = 0; i < 4; i++) ldm4(af[i], ab + 4 * (a_off[i] + kk));
            uint32_t bq[2][4];
#pragma unroll
            for (int jj = 0; jj < 2; jj++) ldm4(bq[jj], wb + 4 * (b_off[jj] + kk));
#pragma unroll
            for (int i = 0; i < 4; i++)
#pragma unroll
                for (int j = 0; j < 4; j++)
                    mma_tf32(c[i][j], af[i],
                             bq[j >> 1][(j & 1) * 2], bq[j >> 1][(j & 1) * 2 + 1]);
        }
        buf ^= 1;   // safe: next write to this buf is fenced by next iter's barrier
    }

#pragma unroll
    for (int i = 0; i < 4; i++) {
#pragma unroll
        for (int j = 0; j < 4; j++) {
            const int orow = bm + rb + i * 16 + gid;
            const int ocol = bn + nb + j * 8 + tig * 2;
            *(float2*)(C + (size_t)orow * N + ocol)       = make_float2(c[i][j][0], c[i][j][1]);
            *(float2*)(C + (size_t)(orow + 8) * N + ocol) = make_float2(c[i][j][2], c[i][j][3]);
        }
    }
}

#define GSMEM (4 * BUFSZ * 4)    // 73728 bytes

__global__ void __launch_bounds__(256) gemm_tf32(const float* __restrict__ A,
                                                 const float* __restrict__ W,
                                                 float* __restrict__ C, int N) {
    gemm_tf32_body(A, W, C, N, blockIdx.y * 128, blockIdx.x * 128);
}

__global__ void __launch_bounds__(256) gemm_tf32_kv(const float* __restrict__ A,
                                                    const float* __restrict__ Wk,
                                                    const float* __restrict__ Wv,
                                                    float* __restrict__ Ck,
                                                    float* __restrict__ Cv, int N) {
    const float* W = (blockIdx.z == 0) ? Wk : Wv;
    float*       C = (blockIdx.z == 0) ? Ck : Cv;
    gemm_tf32_body(A, W, C, N, blockIdx.y * 128, blockIdx.x * 128);
}

// ---------------------------------------------------------------------------
// Fused per-head RMSNorm + RoPE (validated)
// ---------------------------------------------------------------------------
__global__ void __launch_bounds__(256) norm_rope(float* __restrict__ t,
                                                 const float* __restrict__ w,
                                                 const float* __restrict__ cosT,
                                                 const float* __restrict__ sinT,
                                                 int heads, int nrows) {
    const int warp = blockIdx.x * (blockDim.x >> 5) + (threadIdx.x >> 5);
    if (warp >= nrows) return;
    const int lane = threadIdx.x & 31;
    const int s = (warp / heads) % S_;

    float* row = t + (size_t)warp * HD_;
    float a = row[lane];
    float b = row[lane + 32];

    float ss = a * a + b * b;
#pragma unroll
    for (int o = 16; o > 0; o >>= 1) ss += __shfl_xor_sync(0xffffffffu, ss, o);

    const float r = rsqrtf(ss * (1.0f / 64.0f) + 1e-6f);
    const float n0 = a * r * w[lane];
    const float n1 = b * r * w[lane + 32];

    const float c0 = cosT[s * HD_ + lane];
    const float s0 = sinT[s * HD_ + lane];
    const float c1 = cosT[s * HD_ + lane + 32];
    const float s1 = sinT[s * HD_ + lane + 32];

    row[lane]      = n0 * c0 - n1 * s0;
    row[lane + 32] = n1 * c1 + n0 * s1;
}

// ---------------------------------------------------------------------------
// bf16 helpers for split-precision tensor-core attention (validated R6-R8)
// ---------------------------------------------------------------------------
__device__ __forceinline__ uint32_t packbf(float x0, float x1) {
    uint32_t r;
    asm("cvt.rn.bf16x2.f32 %0, %1, %2;" : "=r"(r) : "f"(x1), "f"(x0));
    return r;
}
__device__ __forceinline__ void splitpack(float x0, float x1,
                                          uint32_t& hi, uint32_t& lo) {
    hi = packbf(x0, x1);
    __nv_bfloat162 hb = *(__nv_bfloat162*)&hi;
    lo = packbf(x0 - __bfloat162float(hb.x), x1 - __bfloat162float(hb.y));
}
__device__ __forceinline__ void mma_bf16(float c[4],
                                         const uint32_t a[4],
                                         uint32_t b0, uint32_t b1) {
    asm volatile(
        "mma.sync.aligned.m16n8k16.row.col.f32.bf16.bf16.f32 "
        "{%0,%1,%2,%3}, {%4,%5,%6,%7}, {%8,%9}, {%0,%1,%2,%3};"
        : "+f"(c[0]), "+f"(c[1]), "+f"(c[2]), "+f"(c[3])
        : "r"(a[0]), "r"(a[1]), "r"(a[2]), "r"(a[3]), "r"(b0), "r"(b1));
}
__device__ __forceinline__ void ldm4t(uint32_t r[4], uint32_t addr) {
    asm volatile(
        "ldmatrix.sync.aligned.m8n8.x4.trans.shared.b16 {%0,%1,%2,%3}, [%4];"
        : "=r"(r[0]), "=r"(r[1]), "=r"(r[2]), "=r"(r[3]) : "r"(addr));
}

// ---------------------------------------------------------------------------
// Tensor-core causal flash attention, split-bf16 (validated R6-R8)
// ---------------------------------------------------------------------------
#define KVST 72

__global__ void __launch_bounds__(128) attn_tc(const float* __restrict__ q,
                                               const float* __restrict__ k,
                                               const float* __restrict__ v,
                                               float* __restrict__ o) {
    __shared__ unsigned short ksh_hi[32][KVST], ksh_lo[32][KVST];
    __shared__ unsigned short vsh_hi[32][KVST], vsh_lo[32][KVST];

    const int t    = threadIdx.x;
    const int lane = t & 31;
    const int w    = t >> 5;
    const int gid  = lane >> 2;
    const int tig  = lane & 3;
    const int b    = blockIdx.z;
    const int h    = blockIdx.y;
    const int kh   = h >> 2;
    const int qb   = blockIdx.x * 64;
    const int r0   = qb + w * 16 + gid;

    uint32_t qh[4][4], ql[4][4];
    {
        const float* q0 = q + ((size_t)(b * S_ + r0) * H_ + h) * HD_;
        const float* q1 = q0 + (size_t)8 * H_ * HD_;
#pragma unroll
        for (int kc = 0; kc < 4; kc++) {
            const int d0 = kc * 16 + tig * 2;
            float2 x00 = *(const float2*)(q0 + d0);
            float2 x10 = *(const float2*)(q1 + d0);
            float2 x02 = *(const float2*)(q0 + d0 + 8);
            float2 x12 = *(const float2*)(q1 + d0 + 8);
            splitpack(x00.x * 0.125f, x00.y * 0.125f, qh[kc][0], ql[kc][0]);
            splitpack(x10.x * 0.125f, x10.y * 0.125f, qh[kc][1], ql[kc][1]);
            splitpack(x02.x * 0.125f, x02.y * 0.125f, qh[kc][2], ql[kc][2]);
            splitpack(x12.x * 0.125f, x12.y * 0.125f, qh[kc][3], ql[kc][3]);
        }
    }

    float oc[8][4];
#pragma unroll
    for (int nt = 0; nt < 8; nt++)
#pragma unroll
        for (int r = 0; r < 4; r++) oc[nt][r] = 0.f;
    float m0 = -1e30f, m1 = -1e30f, l0 = 0.f, l1 = 0.f;

    const uint32_t vhi_base = (uint32_t)__cvta_generic_to_shared(&vsh_hi[0][0]);
    const uint32_t vlo_base = (uint32_t)__cvta_generic_to_shared(&vsh_lo[0][0]);
    const int lm_key = lane & 15;
    const int lm_d   = (lane >> 4) * 8;

    for (int n0 = 0; n0 < qb + 64; n0 += 32) {
#pragma unroll
        for (int i = 0; i < 4; i++) {
            const int idx = t + i * 128;
            const int key = idx >> 4;
            const int c   = idx & 15;
            const size_t base = ((size_t)(b * S_ + n0 + key) * KVH_ + kh) * HD_ + c * 4;
            float4 kk = *(const float4*)(k + base);
            float4 vv = *(const float4*)(v + base);
            uint32_t h0, h1, lo0, lo1;
            splitpack(kk.x, kk.y, h0, lo0);
            splitpack(kk.z, kk.w, h1, lo1);
            *(uint2*)&ksh_hi[key][c * 4] = make_uint2(h0, h1);
            *(uint2*)&ksh_lo[key][c * 4] = make_uint2(lo0, lo1);
            splitpack(vv.x, vv.y, h0, lo0);
            splitpack(vv.z, vv.w, h1, lo1);
            *(uint2*)&vsh_hi[key][c * 4] = make_uint2(h0, h1);
            *(uint2*)&vsh_lo[key][c * 4] = make_uint2(lo0, lo1);
        }
        __syncthreads();

        const bool active = (n0 <= qb + w * 16 + 15);
        if (active) {
            float sc[4][4];
#pragma unroll
            for (int j = 0; j < 4; j++)
#pragma unroll
                for (int r = 0; r < 4; r++) sc[j][r] = 0.f;

#pragma unroll
            for (int j = 0; j < 4; j++) {
                const int key = j * 8 + gid;
#pragma unroll
                for (int kc = 0; kc < 4; kc++) {
                    const int d = kc * 16 + tig * 2;
                    uint32_t bh0 = *(const uint32_t*)&ksh_hi[key][d];
                    uint32_t bh1 = *(const uint32_t*)&ksh_hi[key][d + 8];
                    uint32_t bl0 = *(const uint32_t*)&ksh_lo[key][d];
                    uint32_t bl1 = *(const uint32_t*)&ksh_lo[key][d + 8];
                    mma_bf16(sc[j], qh[kc], bh0, bh1);
                    mma_bf16(sc[j], qh[kc], bl0, bl1);
                    mma_bf16(sc[j], ql[kc], bh0, bh1);
                }
            }

            if (n0 + 31 > qb + w * 16) {
#pragma unroll
                for (int j = 0; j < 4; j++) {
                    const int col = n0 + j * 8 + tig * 2;
                    if (col     > r0)     sc[j][0] = -1e30f;
                    if (col + 1 > r0)     sc[j][1] = -1e30f;
                    if (col     > r0 + 8) sc[j][2] = -1e30f;
                    if (col + 1 > r0 + 8) sc[j][3] = -1e30f;
                }
            }

            float tm0 = -1e30f, tm1 = -1e30f;
#pragma unroll
            for (int j = 0; j < 4; j++) {
                tm0 = fmaxf(tm0, fmaxf(sc[j][0], sc[j][1]));
                tm1 = fmaxf(tm1, fmaxf(sc[j][2], sc[j][3]));
            }
            tm0 = fmaxf(tm0, __shfl_xor_sync(0xffffffffu, tm0, 1));
            tm0 = fmaxf(tm0, __shfl_xor_sync(0xffffffffu, tm0, 2));
            tm1 = fmaxf(tm1, __shfl_xor_sync(0xffffffffu, tm1, 1));
            tm1 = fmaxf(tm1, __shfl_xor_sync(0xffffffffu, tm1, 2));

            const float mn0 = fmaxf(m0, tm0);
            const float mn1 = fmaxf(m1, tm1);
            const float al0 = exp2f((m0 - mn0) * LOG2E);
            const float al1 = exp2f((m1 - mn1) * LOG2E);
            m0 = mn0;  m1 = mn1;
            l0 *= al0; l1 *= al1;
#pragma unroll
            for (int nt = 0; nt < 8; nt++) {
                oc[nt][0] *= al0; oc[nt][1] *= al0;
                oc[nt][2] *= al1; oc[nt][3] *= al1;
            }
#pragma unroll
            for (int j = 0; j < 4; j++) {
                sc[j][0] = exp2f((sc[j][0] - mn0) * LOG2E);
                sc[j][1] = exp2f((sc[j][1] - mn0) * LOG2E);
                sc[j][2] = exp2f((sc[j][2] - mn1) * LOG2E);
                sc[j][3] = exp2f((sc[j][3] - mn1) * LOG2E);
                l0 += sc[j][0] + sc[j][1];
                l1 += sc[j][2] + sc[j][3];
            }

#pragma unroll
            for (int kc2 = 0; kc2 < 2; kc2++) {
                uint32_t pah[4], pal[4];
                splitpack(sc[2 * kc2][0],     sc[2 * kc2][1],     pah[0], pal[0]);
                splitpack(sc[2 * kc2][2],     sc[2 * kc2][3],     pah[1], pal[1]);
                splitpack(sc[2 * kc2 + 1][0], sc[2 * kc2 + 1][1], pah[2], pal[2]);
                splitpack(sc[2 * kc2 + 1][2], sc[2 * kc2 + 1][3], pah[3], pal[3]);
#pragma unroll
                for (int ntp = 0; ntp < 4; ntp++) {
                    const uint32_t off =
                        (uint32_t)(((kc2 * 16 + lm_key) * KVST + ntp * 16 + lm_d) * 2);
                    uint32_t vh[4], vl[4];
                    ldm4t(vh, vhi_base + off);
                    ldm4t(vl, vlo_base + off);
                    mma_bf16(oc[2 * ntp],     pah, vh[0], vh[1]);
                    mma_bf16(oc[2 * ntp],     pah, vl[0], vl[1]);
                    mma_bf16(oc[2 * ntp],     pal, vh[0], vh[1]);
                    mma_bf16(oc[2 * ntp + 1], pah, vh[2], vh[3]);
                    mma_bf16(oc[2 * ntp + 1], pah, vl[2], vl[3]);
                    mma_bf16(oc[2 * ntp + 1], pal, vh[2], vh[3]);
                }
            }
        }
        __syncthreads();
    }

    l0 += __shfl_xor_sync(0xffffffffu, l0, 1);
    l0 += __shfl_xor_sync(0xffffffffu, l0, 2);
    l1 += __shfl_xor_sync(0xffffffffu, l1, 1);
    l1 += __shfl_xor_sync(0xffffffffu, l1, 2);
    const float inv0 = 1.f / l0;
    const float inv1 = 1.f / l1;

    float* o0 = o + ((size_t)(b * S_ + r0) * H_ + h) * HD_;
    float* o1 = o0 + (size_t)8 * H_ * HD_;
#pragma unroll
    for (int nt = 0; nt < 8; nt++) {
        *(float2*)(o0 + nt * 8 + tig * 2) =
            make_float2(oc[nt][0] * inv0, oc[nt][1] * inv0);
        *(float2*)(o1 + nt * 8 + tig * 2) =
            make_float2(oc[nt][2] * inv1, oc[nt][3] * inv1);
    }
}

// ---------------------------------------------------------------------------
extern "C" void kernel_launch(void* const* d_in, const int* in_sizes, int n_in,
                              void* d_out, int out_size) {
    const float* x     = (const float*)d_in[0];
    // d_in[1] = mask (unused; causal hardcoded)
    const float* cosT  = (const float*)d_in[2];
    const float* sinT  = (const float*)d_in[3];
    const float* Wq    = (const float*)d_in[4];
    const float* Wk    = (const float*)d_in[5];
    const float* Wv    = (const float*)d_in[6];
    const float* Wo    = (const float*)d_in[7];
    const float* wqn   = (const float*)d_in[8];
    const float* wkn   = (const float*)d_in[9];
    float* out = (float*)d_out;

    float *q, *k, *v, *o;
    cudaGetSymbolAddress((void**)&q, g_q);
    cudaGetSymbolAddress((void**)&k, g_k);
    cudaGetSymbolAddress((void**)&v, g_v);
    cudaGetSymbolAddress((void**)&o, g_o);

    cudaFuncSetAttribute(gemm_tf32,    cudaFuncAttributeMaxDynamicSharedMemorySize, GSMEM);
    cudaFuncSetAttribute(gemm_tf32_kv, cudaFuncAttributeMaxDynamicSharedMemorySize, GSMEM);

    // Q projection
    gemm_tf32<<<dim3((H_ * HD_) / 128, MROWS / 128), 256, GSMEM>>>(x, Wq, q, H_ * HD_);
    // K+V projections fused
    gemm_tf32_kv<<<dim3((KVH_ * HD_) / 128, MROWS / 128, 2), 256, GSMEM>>>(x, Wk, Wv, k, v,
                                                                           KVH_ * HD_);

    // fused RMSNorm + RoPE on q and k
    {
        const int qrows = MROWS * H_;
        const int krows = MROWS * KVH_;
        norm_rope<<<(qrows + 7) / 8, 256>>>(q, wqn, cosT, sinT, H_, qrows);
        norm_rope<<<(krows + 7) / 8, 256>>>(k, wkn, cosT, sinT, KVH_, krows);
    }

    // causal GQA attention (split-bf16 tensor cores)
    attn_tc<<<dim3(S_ / 64, H_, B_), 128>>>(q, k, v, o);

    // output projection
    gemm_tf32<<<dim3(DIN_ / 128, MROWS / 128), 256, GSMEM>>>(o, Wo, out, DIN_);
}